// round 4
// baseline (speedup 1.0000x reference)
#include <cuda_runtime.h>
#include <cuda_bf16.h>
#include <cstdint>

#define NMAX 100000
#define EMAX 1600000
#define DIN  256
#define F    64
#define C2   128

// ---------------- scratch (device globals: allocation-free rule) ----------------
__device__ float  g_ZH[(size_t)NMAX * C2];   // Z pre-activation, then H in-place
__device__ float4 g_Q[NMAX];                 // per-node score scalars, pre-scaled by 1/||a||
__device__ float  g_w[6 * F];                // folded a-vector combos
__device__ float  g_scal[4];                 // inv_norm_high, inv_norm_low, theta_high, theta_low
__device__ int    g_maxZ[2];
__device__ int    g_maxO;
__device__ int    g_deg[NMAX];
__device__ int    g_rs[NMAX];                // CSR row start (exclusive prefix of deg)
__device__ int    g_cur[NMAX];               // fill cursors
__device__ int    g_csr[EMAX];               // dst indices grouped by src
// Pre-split, pre-transposed B = [Wh|Wl]: [128 n][256 k] bf16 hi/lo images (L2-hot).
__device__ __align__(16) __nv_bfloat16 g_Bt_h[128 * 256];
__device__ __align__(16) __nv_bfloat16 g_Bt_l[128 * 256];

__device__ __forceinline__ float leaky(float x) { return fmaxf(x, 0.2f * x); }

__device__ __forceinline__ uint32_t smem_u32(const void* p) {
    uint32_t a;
    asm("{ .reg .u64 t; cvta.to.shared.u64 t, %1; cvt.u32.u64 %0, t; }" : "=r"(a) : "l"(p));
    return a;
}

__device__ __forceinline__ void split_bf16(float x, __nv_bfloat16& hi, __nv_bfloat16& lo) {
    hi = __float2bfloat16(x);
    lo = __float2bfloat16(x - __bfloat162float(hi));
}

#define LDMX4(r0, r1, r2, r3, addr) \
    asm volatile("ldmatrix.sync.aligned.m8n8.x4.shared.b16 {%0,%1,%2,%3}, [%4];" \
                 : "=r"(r0), "=r"(r1), "=r"(r2), "=r"(r3) : "r"(addr))

#define MMA16816(d, a, b0, b1) \
    asm volatile("mma.sync.aligned.m16n8k16.row.col.f32.bf16.bf16.f32 " \
                 "{%0,%1,%2,%3}, {%4,%5,%6,%7}, {%8,%9}, {%0,%1,%2,%3};" \
                 : "+f"((d)[0]), "+f"((d)[1]), "+f"((d)[2]), "+f"((d)[3]) \
                 : "r"((a)[0]), "r"((a)[1]), "r"((a)[2]), "r"((a)[3]), "r"(b0), "r"(b1))

// ---------------- K0: norms, thetas, folded weight vectors ----------------
__global__ void prep_kernel(const float* __restrict__ ah, const float* __restrict__ al,
                            const float* __restrict__ ch, const float* __restrict__ cl) {
    __shared__ float sh[256], sl[256];
    int t = threadIdx.x;
    float vh = ah[t], vl = al[t];
    sh[t] = vh * vh; sl[t] = vl * vl;
    __syncthreads();
    for (int o = 128; o; o >>= 1) {
        if (t < o) { sh[t] += sh[t + o]; sl[t] += sl[t + o]; }
        __syncthreads();
    }
    if (t == 0) {
        g_scal[0] = 1.0f / sqrtf(sh[0]);
        g_scal[1] = 1.0f / sqrtf(sl[0]);
        float c = ch[0];
        g_scal[2] = (fminf(fmaxf(c + 3.0f, 0.0f), 6.0f) / 3.0f + 1e-6f) * 0.5f;
        c = cl[0];
        g_scal[3] = (fminf(fmaxf(c + 3.0f, 0.0f), 6.0f) / 3.0f + 1e-6f) * 0.5f;
        g_maxZ[0] = 0; g_maxZ[1] = 0; g_maxO = 0;
    }
    if (t < F) {
        g_w[t]         = ah[t]     + ah[2*F+t] + ah[3*F+t];
        g_w[F + t]     = ah[F+t]   + ah[2*F+t] - ah[3*F+t];
        g_w[2*F + t]   = al[t];
        g_w[3*F + t]   = al[F+t];
        g_w[4*F + t]   = al[2*F+t] + al[3*F+t];
        g_w[5*F + t]   = al[2*F+t] - al[3*F+t];
    }
}

// ---------------- K0b: build split/transposed B images ----------------
__global__ void prep_b_kernel(const float* __restrict__ Wh, const float* __restrict__ Wl) {
    int e = blockIdx.x * blockDim.x + threadIdx.x;   // 0..32767
    int n = e >> 8;
    int k = e & 255;
    float v = (n < 64) ? Wh[(size_t)k * F + n] : Wl[(size_t)k * F + (n - 64)];
    __nv_bfloat16 hi, lo;
    split_bf16(v, hi, lo);
    g_Bt_h[e] = hi;
    g_Bt_l[e] = lo;
}

// ---------------- CSR build ----------------
__global__ void zero_deg_kernel(int N) {
    int i = blockIdx.x * blockDim.x + threadIdx.x;
    if (i < N) g_deg[i] = 0;
}

__global__ void count_kernel(const int* __restrict__ src, int E) {
    int i = blockIdx.x * blockDim.x + threadIdx.x;
    int stride = gridDim.x * blockDim.x;
    for (int e = i; e < E; e += stride) atomicAdd(&g_deg[__ldg(src + e)], 1);
}

__global__ void scan_kernel(int N) {
    __shared__ int part[1024];
    int t = threadIdx.x;
    int C = (N + 1023) >> 10;
    int base = t * C;
    int s = 0;
    for (int i = 0; i < C; i++) {
        int idx = base + i;
        if (idx < N) s += g_deg[idx];
    }
    part[t] = s;
    __syncthreads();
    for (int o = 1; o < 1024; o <<= 1) {
        int v = (t >= o) ? part[t - o] : 0;
        __syncthreads();
        part[t] += v;
        __syncthreads();
    }
    int run = part[t] - s;   // exclusive start of this thread's chunk
    for (int i = 0; i < C; i++) {
        int idx = base + i;
        if (idx < N) {
            g_rs[idx]  = run;
            g_cur[idx] = run;
            run += g_deg[idx];
        }
    }
}

__global__ void fill_kernel(const int* __restrict__ src, const int* __restrict__ dst, int E) {
    int i = blockIdx.x * blockDim.x + threadIdx.x;
    int stride = gridDim.x * blockDim.x;
    for (int e = i; e < E; e += stride) {
        int s = __ldg(src + e);
        int pos = atomicAdd(&g_cur[s], 1);
        g_csr[pos] = __ldg(dst + e);
    }
}

// ---------------- K1: HMMA split-bf16 GEMM, register-prefetch pipelined ----------------
#define ASTRIDE 40   // bf16 elements per smem row (32 + 8 pad)

__global__ void __launch_bounds__(256) gemm_tc_kernel(const float* __restrict__ X, int N) {
    __shared__ __nv_bfloat16 As_h[128 * ASTRIDE];
    __shared__ __nv_bfloat16 As_l[128 * ASTRIDE];
    __shared__ __nv_bfloat16 Bs_h[128 * ASTRIDE];
    __shared__ __nv_bfloat16 Bs_l[128 * ASTRIDE];
    __shared__ int smax[2];

    int tid  = threadIdx.x;
    int wid  = tid >> 5;
    int lane = tid & 31;
    int brow = blockIdx.x * 128;
    int warp_m = wid & 3;
    int warp_n = wid >> 2;

    if (tid < 2) smax[tid] = 0;

    float acc[2][8][4];
    #pragma unroll
    for (int mi = 0; mi < 2; mi++)
        #pragma unroll
        for (int ni = 0; ni < 8; ni++)
            #pragma unroll
            for (int q = 0; q < 4; q++) acc[mi][ni][q] = 0.f;

    uint32_t sbAH = smem_u32(As_h), sbAL = smem_u32(As_l);
    uint32_t sbBH = smem_u32(Bs_h), sbBL = smem_u32(Bs_l);

    int a_r = lane & 15, a_c = (lane >> 4) << 3;
    int b_r = lane & 7;
    int b_n = ((lane >> 4) & 1) << 3;
    int b_k = ((lane >> 3) & 1) << 3;

    // per-thread load indices
    int arow[4], ac4[4];
    #pragma unroll
    for (int i = 0; i < 4; i++) {
        int idx = tid + 256 * i;
        arow[i] = idx >> 3;
        ac4[i]  = (idx & 7) << 2;
    }
    int bn[2], bk[2];
    #pragma unroll
    for (int i = 0; i < 2; i++) {
        int idx = tid + 256 * i;
        bn[i] = idx >> 2;
        bk[i] = (idx & 3) << 3;
    }

    float4 xa[4];
    uint4  pbh[2], pbl[2];

    // prologue: prefetch chunk 0
    #pragma unroll
    for (int i = 0; i < 4; i++) {
        int grow = brow + arow[i];
        xa[i] = (grow < N) ? *(const float4*)(X + (size_t)grow * DIN + ac4[i])
                           : make_float4(0.f, 0.f, 0.f, 0.f);
    }
    #pragma unroll
    for (int i = 0; i < 2; i++) {
        pbh[i] = *(const uint4*)(g_Bt_h + (size_t)bn[i] * 256 + bk[i]);
        pbl[i] = *(const uint4*)(g_Bt_l + (size_t)bn[i] * 256 + bk[i]);
    }

    for (int chunk = 0; chunk < 8; chunk++) {
        __syncthreads();   // smem free (prev MMA done)
        // store prefetched A (convert) and B
        #pragma unroll
        for (int i = 0; i < 4; i++) {
            float4 v = xa[i];
            __nv_bfloat16 h0, h1, h2, h3, l0, l1, l2, l3;
            split_bf16(v.x, h0, l0); split_bf16(v.y, h1, l1);
            split_bf16(v.z, h2, l2); split_bf16(v.w, h3, l3);
            int o = arow[i] * ASTRIDE + ac4[i];
            __nv_bfloat162 p;
            p.x = h0; p.y = h1; *(__nv_bfloat162*)&As_h[o]     = p;
            p.x = h2; p.y = h3; *(__nv_bfloat162*)&As_h[o + 2] = p;
            p.x = l0; p.y = l1; *(__nv_bfloat162*)&As_l[o]     = p;
            p.x = l2; p.y = l3; *(__nv_bfloat162*)&As_l[o + 2] = p;
        }
        #pragma unroll
        for (int i = 0; i < 2; i++) {
            *(uint4*)&Bs_h[bn[i] * ASTRIDE + bk[i]] = pbh[i];
            *(uint4*)&Bs_l[bn[i] * ASTRIDE + bk[i]] = pbl[i];
        }
        __syncthreads();   // smem ready

        // prefetch next chunk while MMAs run
        if (chunk < 7) {
            int k0 = (chunk + 1) * 32;
            #pragma unroll
            for (int i = 0; i < 4; i++) {
                int grow = brow + arow[i];
                xa[i] = (grow < N) ? *(const float4*)(X + (size_t)grow * DIN + k0 + ac4[i])
                                   : make_float4(0.f, 0.f, 0.f, 0.f);
            }
            #pragma unroll
            for (int i = 0; i < 2; i++) {
                pbh[i] = *(const uint4*)(g_Bt_h + (size_t)bn[i] * 256 + k0 + bk[i]);
                pbl[i] = *(const uint4*)(g_Bt_l + (size_t)bn[i] * 256 + k0 + bk[i]);
            }
        }

        #pragma unroll
        for (int ks = 0; ks < 2; ks++) {
            int k16 = ks * 16;
            uint32_t ah[2][4], al[2][4];
            #pragma unroll
            for (int mi = 0; mi < 2; mi++) {
                uint32_t aoff = ((warp_m * 32 + mi * 16 + a_r) * ASTRIDE + k16 + a_c) * 2;
                LDMX4(ah[mi][0], ah[mi][1], ah[mi][2], ah[mi][3], sbAH + aoff);
                LDMX4(al[mi][0], al[mi][1], al[mi][2], al[mi][3], sbAL + aoff);
            }
            #pragma unroll
            for (int np = 0; np < 4; np++) {
                uint32_t boff = ((warp_n * 64 + np * 16 + b_n + b_r) * ASTRIDE + k16 + b_k) * 2;
                uint32_t bh[4], bl[4];
                LDMX4(bh[0], bh[1], bh[2], bh[3], sbBH + boff);
                LDMX4(bl[0], bl[1], bl[2], bl[3], sbBL + boff);
                #pragma unroll
                for (int mi = 0; mi < 2; mi++) {
                    #pragma unroll
                    for (int h = 0; h < 2; h++) {
                        float* d = acc[mi][np * 2 + h];
                        MMA16816(d, ah[mi], bh[2 * h], bh[2 * h + 1]);
                        MMA16816(d, ah[mi], bl[2 * h], bl[2 * h + 1]);
                        MMA16816(d, al[mi], bh[2 * h], bh[2 * h + 1]);
                    }
                }
            }
        }
    }

    // --- Epilogue: store fragments + per-branch |max| ---
    float mymax = 0.f;
    int row0 = brow + warp_m * 32 + (lane >> 2);
    int col0 = warp_n * 64 + ((lane & 3) << 1);
    #pragma unroll
    for (int mi = 0; mi < 2; mi++) {
        int r0 = row0 + mi * 16;
        #pragma unroll
        for (int ni = 0; ni < 8; ni++) {
            int c = col0 + ni * 8;
            float* d = acc[mi][ni];
            if (r0 < N) {
                *(float2*)&g_ZH[(size_t)r0 * C2 + c] = make_float2(d[0], d[1]);
                mymax = fmaxf(mymax, fmaxf(fabsf(d[0]), fabsf(d[1])));
            }
            if (r0 + 8 < N) {
                *(float2*)&g_ZH[(size_t)(r0 + 8) * C2 + c] = make_float2(d[2], d[3]);
                mymax = fmaxf(mymax, fmaxf(fabsf(d[2]), fabsf(d[3])));
            }
        }
    }
    atomicMax(&smax[warp_n], __float_as_int(mymax));
    __syncthreads();
    if (tid < 2) atomicMax(&g_maxZ[tid], smax[tid]);
}

// ---------------- K2: relu_bt + per-node score scalars; warp per node ----------------
__device__ __forceinline__ float dot4v(float4 h, float4 w) {
    return fmaf(h.x, w.x, fmaf(h.y, w.y, fmaf(h.z, w.z, h.w * w.w)));
}

__global__ void act_kernel(int N) {
    int gw   = (int)(((size_t)blockIdx.x * blockDim.x + threadIdx.x) >> 5);
    int lane = threadIdx.x & 31;
    if (gw >= N) return;
    float th = __int_as_float(g_maxZ[0]);
    float tl = __int_as_float(g_maxZ[1]);
    float t  = (lane < 16) ? th : tl;
    float4 z = *(float4*)&g_ZH[(size_t)gw * C2 + lane * 4];
    float4 h;
    h.x = fminf(leaky(z.x), t); h.y = fminf(leaky(z.y), t);
    h.z = fminf(leaky(z.z), t); h.w = fminf(leaky(z.w), t);
    *(float4*)&g_ZH[(size_t)gw * C2 + lane * 4] = h;

    const float4* W4 = (const float4*)g_w;
    float p0 = 0.f, p1 = 0.f, p2 = 0.f, p3 = 0.f;
    if (lane < 16) {
        p0 = dot4v(h, __ldg(W4 + lane));
        p1 = dot4v(h, __ldg(W4 + 16 + lane));
        p2 = dot4v(h, __ldg(W4 + 32 + lane));
        p3 = dot4v(h, __ldg(W4 + 48 + lane));
    } else {
        p2 = dot4v(h, __ldg(W4 + 48 + lane));
        p3 = dot4v(h, __ldg(W4 + 64 + lane));
    }
    #pragma unroll
    for (int o = 16; o; o >>= 1) {
        p0 += __shfl_down_sync(0xffffffffu, p0, o);
        p1 += __shfl_down_sync(0xffffffffu, p1, o);
        p2 += __shfl_down_sync(0xffffffffu, p2, o);
        p3 += __shfl_down_sync(0xffffffffu, p3, o);
    }
    if (lane == 0) {
        float inh = g_scal[0], inl = g_scal[1];
        g_Q[gw] = make_float4(p0 * inh, p1 * inh, p2 * inl, p3 * inl);
    }
}

// ---------------- K3: CSR gather aggregation, warp per node ----------------
__global__ void __launch_bounds__(256) agg_kernel(float* __restrict__ out, int N) {
    __shared__ int bmax;
    if (threadIdx.x == 0) bmax = 0;
    __syncthreads();
    int gw   = (int)(((size_t)blockIdx.x * blockDim.x + threadIdx.x) >> 5);
    int lane = threadIdx.x & 31;
    float m = 0.f;
    if (gw < N) {
        float4 qs = g_Q[gw];
        int start = g_rs[gw];
        int end   = start + g_deg[gw];
        bool hi = lane < 16;
        float4 acc = make_float4(0.f, 0.f, 0.f, 0.f);
        float rsh = 0.f, rsl = 0.f;
        int dnext = (start < end) ? __ldg(&g_csr[start]) : 0;
        for (int j = start; j < end; j++) {
            int d = dnext;
            if (j + 1 < end) dnext = __ldg(&g_csr[j + 1]);
            float4 qd = __ldg(&g_Q[d]);
            float sch = qs.x + qd.y;
            float scl = qs.z + qd.w;
            float eh = __expf(-fmaxf(sch, 0.2f * sch));
            float el = __expf(-fmaxf(scl, 0.2f * scl));
            rsh += eh; rsl += el;
            float4 hv = *(const float4*)&g_ZH[(size_t)d * C2 + lane * 4];
            float ec = hi ? eh : el;
            acc.x = fmaf(hv.x, ec, acc.x);
            acc.y = fmaf(hv.y, ec, acc.y);
            acc.z = fmaf(hv.z, ec, acc.z);
            acc.w = fmaf(hv.w, ec, acc.w);
        }
        float theta = hi ? g_scal[2] : g_scal[3];
        float inv = 1.0f / ((hi ? rsh : rsl) + theta);
        float4 v = make_float4(acc.x * inv, acc.y * inv, acc.z * inv, acc.w * inv);
        *(float4*)(out + (size_t)gw * C2 + lane * 4) = v;
        m = fmaxf(fmaxf(fabsf(v.x), fabsf(v.y)), fmaxf(fabsf(v.z), fabsf(v.w)));
    }
    #pragma unroll
    for (int o = 16; o; o >>= 1) m = fmaxf(m, __shfl_down_sync(0xffffffffu, m, o));
    if (lane == 0) atomicMax(&bmax, __float_as_int(m));
    __syncthreads();
    if (threadIdx.x == 0) atomicMax(&g_maxO, bmax);
}

// ---------------- K4: final relu_bt on output ----------------
__global__ void fin2_kernel(float* __restrict__ out, int N) {
    size_t total4 = (size_t)N * 32;
    size_t i = (size_t)blockIdx.x * blockDim.x + threadIdx.x;
    size_t stride = (size_t)gridDim.x * blockDim.x;
    float t = __int_as_float(g_maxO);
    for (size_t j = i; j < total4; j += stride) {
        float4 v = ((float4*)out)[j];
        v.x = fminf(leaky(v.x), t); v.y = fminf(leaky(v.y), t);
        v.z = fminf(leaky(v.z), t); v.w = fminf(leaky(v.w), t);
        ((float4*)out)[j] = v;
    }
}

extern "C" void kernel_launch(void* const* d_in, const int* in_sizes, int n_in,
                              void* d_out, int out_size) {
    const float* X    = (const float*)d_in[0];
    const int*   edge = (const int*)d_in[1];
    const float* Wh   = (const float*)d_in[2];
    const float* Wl   = (const float*)d_in[3];
    const float* ah   = (const float*)d_in[4];
    const float* al   = (const float*)d_in[5];
    const float* ch   = (const float*)d_in[6];
    const float* cl   = (const float*)d_in[7];
    float* out = (float*)d_out;

    int N = in_sizes[0] / DIN;
    int E = in_sizes[1] / 2;

    prep_kernel<<<1, 256>>>(ah, al, ch, cl);
    prep_b_kernel<<<128, 256>>>(Wh, Wl);
    zero_deg_kernel<<<(N + 1023) / 1024, 1024>>>(N);
    count_kernel<<<2048, 256>>>(edge, E);
    scan_kernel<<<1, 1024>>>(N);
    fill_kernel<<<2048, 256>>>(edge, edge + E, E);
    gemm_tc_kernel<<<(N + 127) / 128, 256>>>(X, N);
    act_kernel<<<(N * 32 + 255) / 256, 256>>>(N);
    agg_kernel<<<(N * 32 + 255) / 256, 256>>>(out, N);
    fin2_kernel<<<2048, 256>>>(out, N);
}

// round 5
// speedup vs baseline: 1.3154x; 1.3154x over previous
#include <cuda_runtime.h>
#include <cuda_bf16.h>
#include <cstdint>

#define NMAX 100000
#define EMAX 1600000
#define DIN  256
#define F    64
#define C2   128

// ---------------- scratch (device globals: allocation-free rule) ----------------
__device__ float  g_ZH[(size_t)NMAX * C2];   // Z pre-activation, then H in-place
__device__ float4 g_Q[NMAX];                 // per-node score scalars, pre-scaled by 1/||a||
__device__ float  g_w[6 * F];                // folded a-vector combos
__device__ float  g_scal[4];                 // inv_norm_high, inv_norm_low, theta_high, theta_low
__device__ int    g_maxZ[2];
__device__ int    g_maxO;
__device__ int    g_deg[NMAX + 4];
__device__ int    g_rs[NMAX + 4];            // CSR row start (exclusive prefix of deg)
__device__ int    g_cur[NMAX + 4];           // fill cursors
__device__ int    g_csr[EMAX];               // dst indices grouped by src
// Pre-split, pre-transposed B = [Wh|Wl]: [128 n][256 k] bf16 hi/lo images (L2-hot).
__device__ __align__(16) __nv_bfloat16 g_Bt_h[128 * 256];
__device__ __align__(16) __nv_bfloat16 g_Bt_l[128 * 256];

__device__ __forceinline__ float leaky(float x) { return fmaxf(x, 0.2f * x); }

__device__ __forceinline__ uint32_t smem_u32(const void* p) {
    uint32_t a;
    asm("{ .reg .u64 t; cvta.to.shared.u64 t, %1; cvt.u32.u64 %0, t; }" : "=r"(a) : "l"(p));
    return a;
}

__device__ __forceinline__ void split_bf16(float x, __nv_bfloat16& hi, __nv_bfloat16& lo) {
    hi = __float2bfloat16(x);
    lo = __float2bfloat16(x - __bfloat162float(hi));
}

#define LDMX4(r0, r1, r2, r3, addr) \
    asm volatile("ldmatrix.sync.aligned.m8n8.x4.shared.b16 {%0,%1,%2,%3}, [%4];" \
                 : "=r"(r0), "=r"(r1), "=r"(r2), "=r"(r3) : "r"(addr))

#define MMA16816(d, a, b0, b1) \
    asm volatile("mma.sync.aligned.m16n8k16.row.col.f32.bf16.bf16.f32 " \
                 "{%0,%1,%2,%3}, {%4,%5,%6,%7}, {%8,%9}, {%0,%1,%2,%3};" \
                 : "+f"((d)[0]), "+f"((d)[1]), "+f"((d)[2]), "+f"((d)[3]) \
                 : "r"((a)[0]), "r"((a)[1]), "r"((a)[2]), "r"((a)[3]), "r"(b0), "r"(b1))

// ---------------- K0: norms, thetas, folded weight vectors ----------------
__global__ void prep_kernel(const float* __restrict__ ah, const float* __restrict__ al,
                            const float* __restrict__ ch, const float* __restrict__ cl) {
    __shared__ float sh[256], sl[256];
    int t = threadIdx.x;
    float vh = ah[t], vl = al[t];
    sh[t] = vh * vh; sl[t] = vl * vl;
    __syncthreads();
    for (int o = 128; o; o >>= 1) {
        if (t < o) { sh[t] += sh[t + o]; sl[t] += sl[t + o]; }
        __syncthreads();
    }
    if (t == 0) {
        g_scal[0] = 1.0f / sqrtf(sh[0]);
        g_scal[1] = 1.0f / sqrtf(sl[0]);
        float c = ch[0];
        g_scal[2] = (fminf(fmaxf(c + 3.0f, 0.0f), 6.0f) / 3.0f + 1e-6f) * 0.5f;
        c = cl[0];
        g_scal[3] = (fminf(fmaxf(c + 3.0f, 0.0f), 6.0f) / 3.0f + 1e-6f) * 0.5f;
        g_maxZ[0] = 0; g_maxZ[1] = 0; g_maxO = 0;
    }
    if (t < F) {
        g_w[t]         = ah[t]     + ah[2*F+t] + ah[3*F+t];
        g_w[F + t]     = ah[F+t]   + ah[2*F+t] - ah[3*F+t];
        g_w[2*F + t]   = al[t];
        g_w[3*F + t]   = al[F+t];
        g_w[4*F + t]   = al[2*F+t] + al[3*F+t];
        g_w[5*F + t]   = al[2*F+t] - al[3*F+t];
    }
}

// ---------------- K0b: build split/transposed B images ----------------
__global__ void prep_b_kernel(const float* __restrict__ Wh, const float* __restrict__ Wl) {
    int e = blockIdx.x * blockDim.x + threadIdx.x;   // 0..32767
    int n = e >> 8;
    int k = e & 255;
    float v = (n < 64) ? Wh[(size_t)k * F + n] : Wl[(size_t)k * F + (n - 64)];
    __nv_bfloat16 hi, lo;
    split_bf16(v, hi, lo);
    g_Bt_h[e] = hi;
    g_Bt_l[e] = lo;
}

// ---------------- CSR build ----------------
__global__ void zero_deg_kernel(int N) {
    int i = blockIdx.x * blockDim.x + threadIdx.x;
    if (i < N + 4) g_deg[i] = 0;
}

__global__ void count_kernel(const int* __restrict__ src, int E) {
    int i = blockIdx.x * blockDim.x + threadIdx.x;
    int stride = gridDim.x * blockDim.x;
    for (int e = i; e < E; e += stride) atomicAdd(&g_deg[__ldg(src + e)], 1);
}

// 1024 threads, contiguous chunks (multiple of 4), int4-vectorized both phases.
__global__ void scan_kernel(int N) {
    __shared__ int part[1024];
    int t = threadIdx.x;
    int Cc = (((N + 1023) >> 10) + 3) & ~3;
    int base = t * Cc;
    int s = 0;
    for (int i = 0; i < Cc; i += 4) {
        int idx = base + i;
        if (idx < N) {
            int4 v = *(const int4*)&g_deg[idx];   // padded; beyond-N entries are 0
            s += v.x + v.y + v.z + v.w;
        }
    }
    part[t] = s;
    __syncthreads();
    for (int o = 1; o < 1024; o <<= 1) {
        int v = (t >= o) ? part[t - o] : 0;
        __syncthreads();
        part[t] += v;
        __syncthreads();
    }
    int run = part[t] - s;   // exclusive start of this thread's chunk
    for (int i = 0; i < Cc; i += 4) {
        int idx = base + i;
        if (idx < N) {
            int4 v = *(const int4*)&g_deg[idx];
            int4 r;
            r.x = run;
            r.y = r.x + v.x;
            r.z = r.y + v.y;
            r.w = r.z + v.z;
            run = r.w + v.w;
            *(int4*)&g_rs[idx]  = r;
            *(int4*)&g_cur[idx] = r;
        }
    }
}

__global__ void fill_kernel(const int* __restrict__ src, const int* __restrict__ dst, int E) {
    int i = blockIdx.x * blockDim.x + threadIdx.x;
    int stride = gridDim.x * blockDim.x;
    for (int e = i; e < E; e += stride) {
        int s = __ldg(src + e);
        int pos = atomicAdd(&g_cur[s], 1);
        g_csr[pos] = __ldg(dst + e);
    }
}

// ---------------- K1: HMMA split-bf16 GEMM, register-prefetch pipelined ----------------
#define ASTRIDE 40   // bf16 elements per smem row (32 + 8 pad)

__global__ void __launch_bounds__(256) gemm_tc_kernel(const float* __restrict__ X, int N) {
    __shared__ __nv_bfloat16 As_h[128 * ASTRIDE];
    __shared__ __nv_bfloat16 As_l[128 * ASTRIDE];
    __shared__ __nv_bfloat16 Bs_h[128 * ASTRIDE];
    __shared__ __nv_bfloat16 Bs_l[128 * ASTRIDE];
    __shared__ int smax[2];

    int tid  = threadIdx.x;
    int wid  = tid >> 5;
    int lane = tid & 31;
    int brow = blockIdx.x * 128;
    int warp_m = wid & 3;
    int warp_n = wid >> 2;

    if (tid < 2) smax[tid] = 0;

    float acc[2][8][4];
    #pragma unroll
    for (int mi = 0; mi < 2; mi++)
        #pragma unroll
        for (int ni = 0; ni < 8; ni++)
            #pragma unroll
            for (int q = 0; q < 4; q++) acc[mi][ni][q] = 0.f;

    uint32_t sbAH = smem_u32(As_h), sbAL = smem_u32(As_l);
    uint32_t sbBH = smem_u32(Bs_h), sbBL = smem_u32(Bs_l);

    int a_r = lane & 15, a_c = (lane >> 4) << 3;
    int b_r = lane & 7;
    int b_n = ((lane >> 4) & 1) << 3;
    int b_k = ((lane >> 3) & 1) << 3;

    int arow[4], ac4[4];
    #pragma unroll
    for (int i = 0; i < 4; i++) {
        int idx = tid + 256 * i;
        arow[i] = idx >> 3;
        ac4[i]  = (idx & 7) << 2;
    }
    int bn[2], bk[2];
    #pragma unroll
    for (int i = 0; i < 2; i++) {
        int idx = tid + 256 * i;
        bn[i] = idx >> 2;
        bk[i] = (idx & 3) << 3;
    }

    float4 xa[4];
    uint4  pbh[2], pbl[2];

    #pragma unroll
    for (int i = 0; i < 4; i++) {
        int grow = brow + arow[i];
        xa[i] = (grow < N) ? *(const float4*)(X + (size_t)grow * DIN + ac4[i])
                           : make_float4(0.f, 0.f, 0.f, 0.f);
    }
    #pragma unroll
    for (int i = 0; i < 2; i++) {
        pbh[i] = *(const uint4*)(g_Bt_h + (size_t)bn[i] * 256 + bk[i]);
        pbl[i] = *(const uint4*)(g_Bt_l + (size_t)bn[i] * 256 + bk[i]);
    }

    for (int chunk = 0; chunk < 8; chunk++) {
        __syncthreads();
        #pragma unroll
        for (int i = 0; i < 4; i++) {
            float4 v = xa[i];
            __nv_bfloat16 h0, h1, h2, h3, l0, l1, l2, l3;
            split_bf16(v.x, h0, l0); split_bf16(v.y, h1, l1);
            split_bf16(v.z, h2, l2); split_bf16(v.w, h3, l3);
            int o = arow[i] * ASTRIDE + ac4[i];
            __nv_bfloat162 p;
            p.x = h0; p.y = h1; *(__nv_bfloat162*)&As_h[o]     = p;
            p.x = h2; p.y = h3; *(__nv_bfloat162*)&As_h[o + 2] = p;
            p.x = l0; p.y = l1; *(__nv_bfloat162*)&As_l[o]     = p;
            p.x = l2; p.y = l3; *(__nv_bfloat162*)&As_l[o + 2] = p;
        }
        #pragma unroll
        for (int i = 0; i < 2; i++) {
            *(uint4*)&Bs_h[bn[i] * ASTRIDE + bk[i]] = pbh[i];
            *(uint4*)&Bs_l[bn[i] * ASTRIDE + bk[i]] = pbl[i];
        }
        __syncthreads();

        if (chunk < 7) {
            int k0 = (chunk + 1) * 32;
            #pragma unroll
            for (int i = 0; i < 4; i++) {
                int grow = brow + arow[i];
                xa[i] = (grow < N) ? *(const float4*)(X + (size_t)grow * DIN + k0 + ac4[i])
                                   : make_float4(0.f, 0.f, 0.f, 0.f);
            }
            #pragma unroll
            for (int i = 0; i < 2; i++) {
                pbh[i] = *(const uint4*)(g_Bt_h + (size_t)bn[i] * 256 + k0 + bk[i]);
                pbl[i] = *(const uint4*)(g_Bt_l + (size_t)bn[i] * 256 + k0 + bk[i]);
            }
        }

        #pragma unroll
        for (int ks = 0; ks < 2; ks++) {
            int k16 = ks * 16;
            uint32_t ah[2][4], al[2][4];
            #pragma unroll
            for (int mi = 0; mi < 2; mi++) {
                uint32_t aoff = ((warp_m * 32 + mi * 16 + a_r) * ASTRIDE + k16 + a_c) * 2;
                LDMX4(ah[mi][0], ah[mi][1], ah[mi][2], ah[mi][3], sbAH + aoff);
                LDMX4(al[mi][0], al[mi][1], al[mi][2], al[mi][3], sbAL + aoff);
            }
            #pragma unroll
            for (int np = 0; np < 4; np++) {
                uint32_t boff = ((warp_n * 64 + np * 16 + b_n + b_r) * ASTRIDE + k16 + b_k) * 2;
                uint32_t bh[4], bl[4];
                LDMX4(bh[0], bh[1], bh[2], bh[3], sbBH + boff);
                LDMX4(bl[0], bl[1], bl[2], bl[3], sbBL + boff);
                #pragma unroll
                for (int mi = 0; mi < 2; mi++) {
                    #pragma unroll
                    for (int h = 0; h < 2; h++) {
                        float* d = acc[mi][np * 2 + h];
                        MMA16816(d, ah[mi], bh[2 * h], bh[2 * h + 1]);
                        MMA16816(d, ah[mi], bl[2 * h], bl[2 * h + 1]);
                        MMA16816(d, al[mi], bh[2 * h], bh[2 * h + 1]);
                    }
                }
            }
        }
    }

    float mymax = 0.f;
    int row0 = brow + warp_m * 32 + (lane >> 2);
    int col0 = warp_n * 64 + ((lane & 3) << 1);
    #pragma unroll
    for (int mi = 0; mi < 2; mi++) {
        int r0 = row0 + mi * 16;
        #pragma unroll
        for (int ni = 0; ni < 8; ni++) {
            int c = col0 + ni * 8;
            float* d = acc[mi][ni];
            if (r0 < N) {
                *(float2*)&g_ZH[(size_t)r0 * C2 + c] = make_float2(d[0], d[1]);
                mymax = fmaxf(mymax, fmaxf(fabsf(d[0]), fabsf(d[1])));
            }
            if (r0 + 8 < N) {
                *(float2*)&g_ZH[(size_t)(r0 + 8) * C2 + c] = make_float2(d[2], d[3]);
                mymax = fmaxf(mymax, fmaxf(fabsf(d[2]), fabsf(d[3])));
            }
        }
    }
    atomicMax(&smax[warp_n], __float_as_int(mymax));
    __syncthreads();
    if (tid < 2) atomicMax(&g_maxZ[tid], smax[tid]);
}

// ---------------- K2: relu_bt + per-node score scalars; warp per node ----------------
__device__ __forceinline__ float dot4v(float4 h, float4 w) {
    return fmaf(h.x, w.x, fmaf(h.y, w.y, fmaf(h.z, w.z, h.w * w.w)));
}

__global__ void act_kernel(int N) {
    int gw   = (int)(((size_t)blockIdx.x * blockDim.x + threadIdx.x) >> 5);
    int lane = threadIdx.x & 31;
    if (gw >= N) return;
    float th = __int_as_float(g_maxZ[0]);
    float tl = __int_as_float(g_maxZ[1]);
    float t  = (lane < 16) ? th : tl;
    float4 z = *(float4*)&g_ZH[(size_t)gw * C2 + lane * 4];
    float4 h;
    h.x = fminf(leaky(z.x), t); h.y = fminf(leaky(z.y), t);
    h.z = fminf(leaky(z.z), t); h.w = fminf(leaky(z.w), t);
    *(float4*)&g_ZH[(size_t)gw * C2 + lane * 4] = h;

    const float4* W4 = (const float4*)g_w;
    float p0 = 0.f, p1 = 0.f, p2 = 0.f, p3 = 0.f;
    if (lane < 16) {
        p0 = dot4v(h, __ldg(W4 + lane));
        p1 = dot4v(h, __ldg(W4 + 16 + lane));
        p2 = dot4v(h, __ldg(W4 + 32 + lane));
        p3 = dot4v(h, __ldg(W4 + 48 + lane));
    } else {
        p2 = dot4v(h, __ldg(W4 + 48 + lane));
        p3 = dot4v(h, __ldg(W4 + 64 + lane));
    }
    #pragma unroll
    for (int o = 16; o; o >>= 1) {
        p0 += __shfl_down_sync(0xffffffffu, p0, o);
        p1 += __shfl_down_sync(0xffffffffu, p1, o);
        p2 += __shfl_down_sync(0xffffffffu, p2, o);
        p3 += __shfl_down_sync(0xffffffffu, p3, o);
    }
    if (lane == 0) {
        float inh = g_scal[0], inl = g_scal[1];
        g_Q[gw] = make_float4(p0 * inh, p1 * inh, p2 * inl, p3 * inl);
    }
}

// ---------------- K3: CSR aggregation, warp per node, edge-parallel two-phase ----------------
__global__ void __launch_bounds__(256) agg_kernel(float* __restrict__ out, int N) {
    __shared__ int bmax;
    if (threadIdx.x == 0) bmax = 0;
    __syncthreads();
    int gw   = (int)(((size_t)blockIdx.x * blockDim.x + threadIdx.x) >> 5);
    int lane = threadIdx.x & 31;
    float m = 0.f;
    if (gw < N) {
        float4 qs = g_Q[gw];
        int start = g_rs[gw];
        int end   = start + g_deg[gw];
        bool hi = lane < 16;
        float4 acc = make_float4(0.f, 0.f, 0.f, 0.f);
        float rsh = 0.f, rsl = 0.f;
        for (int base = start; base < end; base += 32) {
            int cnt = min(32, end - base);
            // phase 1: one edge per lane — coalesced csr load + parallel Q gather
            int   d_l  = 0;
            float eh_l = 0.f, el_l = 0.f;
            if (lane < cnt) {
                d_l = __ldg(&g_csr[base + lane]);
                float4 qd = __ldg(&g_Q[d_l]);
                float sch = qs.x + qd.y;
                float scl = qs.z + qd.w;
                eh_l = __expf(-fmaxf(sch, 0.2f * sch));
                el_l = __expf(-fmaxf(scl, 0.2f * scl));
            }
            rsh += eh_l;
            rsl += el_l;
            // phase 2: broadcast each edge; H row loads are independent -> high MLP
            for (int j = 0; j < cnt; j++) {
                int   dj  = __shfl_sync(0xffffffffu, d_l, j);
                float ehj = __shfl_sync(0xffffffffu, eh_l, j);
                float elj = __shfl_sync(0xffffffffu, el_l, j);
                float4 hv = __ldg((const float4*)&g_ZH[(size_t)dj * C2 + lane * 4]);
                float ec = hi ? ehj : elj;
                acc.x = fmaf(hv.x, ec, acc.x);
                acc.y = fmaf(hv.y, ec, acc.y);
                acc.z = fmaf(hv.z, ec, acc.z);
                acc.w = fmaf(hv.w, ec, acc.w);
            }
        }
        #pragma unroll
        for (int o = 16; o; o >>= 1) {
            rsh += __shfl_xor_sync(0xffffffffu, rsh, o);
            rsl += __shfl_xor_sync(0xffffffffu, rsl, o);
        }
        float theta = hi ? g_scal[2] : g_scal[3];
        float inv = 1.0f / ((hi ? rsh : rsl) + theta);
        float4 v = make_float4(acc.x * inv, acc.y * inv, acc.z * inv, acc.w * inv);
        *(float4*)(out + (size_t)gw * C2 + lane * 4) = v;
        m = fmaxf(fmaxf(fabsf(v.x), fabsf(v.y)), fmaxf(fabsf(v.z), fabsf(v.w)));
    }
    #pragma unroll
    for (int o = 16; o; o >>= 1) m = fmaxf(m, __shfl_down_sync(0xffffffffu, m, o));
    if (lane == 0) atomicMax(&bmax, __float_as_int(m));
    __syncthreads();
    if (threadIdx.x == 0) atomicMax(&g_maxO, bmax);
}

// ---------------- K4: final relu_bt on output ----------------
__global__ void fin2_kernel(float* __restrict__ out, int N) {
    size_t total4 = (size_t)N * 32;
    size_t i = (size_t)blockIdx.x * blockDim.x + threadIdx.x;
    size_t stride = (size_t)gridDim.x * blockDim.x;
    float t = __int_as_float(g_maxO);
    for (size_t j = i; j < total4; j += stride) {
        float4 v = ((float4*)out)[j];
        v.x = fminf(leaky(v.x), t); v.y = fminf(leaky(v.y), t);
        v.z = fminf(leaky(v.z), t); v.w = fminf(leaky(v.w), t);
        ((float4*)out)[j] = v;
    }
}

extern "C" void kernel_launch(void* const* d_in, const int* in_sizes, int n_in,
                              void* d_out, int out_size) {
    const float* X    = (const float*)d_in[0];
    const int*   edge = (const int*)d_in[1];
    const float* Wh   = (const float*)d_in[2];
    const float* Wl   = (const float*)d_in[3];
    const float* ah   = (const float*)d_in[4];
    const float* al   = (const float*)d_in[5];
    const float* ch   = (const float*)d_in[6];
    const float* cl   = (const float*)d_in[7];
    float* out = (float*)d_out;

    int N = in_sizes[0] / DIN;
    int E = in_sizes[1] / 2;

    prep_kernel<<<1, 256>>>(ah, al, ch, cl);
    prep_b_kernel<<<128, 256>>>(Wh, Wl);
    zero_deg_kernel<<<(N + 1027) / 1024, 1024>>>(N);
    count_kernel<<<2048, 256>>>(edge, E);
    scan_kernel<<<1, 1024>>>(N);
    fill_kernel<<<2048, 256>>>(edge, edge + E, E);
    gemm_tc_kernel<<<(N + 127) / 128, 256>>>(X, N);
    act_kernel<<<(N * 32 + 255) / 256, 256>>>(N);
    agg_kernel<<<(N * 32 + 255) / 256, 256>>>(out, N);
    fin2_kernel<<<2048, 256>>>(out, N);
}

// round 8
// speedup vs baseline: 1.4599x; 1.1098x over previous
#include <cuda_runtime.h>
#include <cuda_bf16.h>
#include <cstdint>

#define NMAX 100000
#define EMAX 1600000
#define DIN  256
#define F    64
#define C2   128

// ---------------- scratch (device globals: allocation-free rule) ----------------
__device__ float  g_ZH[(size_t)NMAX * C2];   // H = leaky(X@W) rows
__device__ float4 g_Q[NMAX];                 // per-node score scalars, pre-scaled by 1/||a||
__device__ float  g_w[6 * F];                // folded a-vector combos
__device__ float  g_scal[4];                 // inv_norm_high, inv_norm_low, theta_high, theta_low
__device__ int    g_deg[NMAX + 4];
__device__ int    g_rs[NMAX + 4];            // CSR row start (exclusive prefix of deg)
__device__ int    g_cur[NMAX + 4];           // fill cursors
__device__ int    g_csr[EMAX];               // dst indices grouped by src
// Pre-split, pre-transposed B = [Wh|Wl]: [128 n][256 k] bf16 hi/lo images (L2-hot).
__device__ __align__(16) __nv_bfloat16 g_Bt_h[128 * 256];
__device__ __align__(16) __nv_bfloat16 g_Bt_l[128 * 256];

__device__ __forceinline__ float leaky(float x) { return fmaxf(x, 0.2f * x); }

__device__ __forceinline__ uint32_t smem_u32(const void* p) {
    uint32_t a;
    asm("{ .reg .u64 t; cvta.to.shared.u64 t, %1; cvt.u32.u64 %0, t; }" : "=r"(a) : "l"(p));
    return a;
}

__device__ __forceinline__ void split_bf16(float x, __nv_bfloat16& hi, __nv_bfloat16& lo) {
    hi = __float2bfloat16(x);
    lo = __float2bfloat16(x - __bfloat162float(hi));
}

#define LDMX4(r0, r1, r2, r3, addr) \
    asm volatile("ldmatrix.sync.aligned.m8n8.x4.shared.b16 {%0,%1,%2,%3}, [%4];" \
                 : "=r"(r0), "=r"(r1), "=r"(r2), "=r"(r3) : "r"(addr))

#define MMA16816(d, a, b0, b1) \
    asm volatile("mma.sync.aligned.m16n8k16.row.col.f32.bf16.bf16.f32 " \
                 "{%0,%1,%2,%3}, {%4,%5,%6,%7}, {%8,%9}, {%0,%1,%2,%3};" \
                 : "+f"((d)[0]), "+f"((d)[1]), "+f"((d)[2]), "+f"((d)[3]) \
                 : "r"((a)[0]), "r"((a)[1]), "r"((a)[2]), "r"((a)[3]), "r"(b0), "r"(b1))

// ---------------- K0: norms, thetas, folded weight vectors ----------------
__global__ void prep_kernel(const float* __restrict__ ah, const float* __restrict__ al,
                            const float* __restrict__ ch, const float* __restrict__ cl) {
    __shared__ float sh[256], sl[256];
    int t = threadIdx.x;
    float vh = ah[t], vl = al[t];
    sh[t] = vh * vh; sl[t] = vl * vl;
    __syncthreads();
    for (int o = 128; o; o >>= 1) {
        if (t < o) { sh[t] += sh[t + o]; sl[t] += sl[t + o]; }
        __syncthreads();
    }
    if (t == 0) {
        g_scal[0] = 1.0f / sqrtf(sh[0]);
        g_scal[1] = 1.0f / sqrtf(sl[0]);
        float c = ch[0];
        g_scal[2] = (fminf(fmaxf(c + 3.0f, 0.0f), 6.0f) / 3.0f + 1e-6f) * 0.5f;
        c = cl[0];
        g_scal[3] = (fminf(fmaxf(c + 3.0f, 0.0f), 6.0f) / 3.0f + 1e-6f) * 0.5f;
    }
    if (t < F) {
        g_w[t]         = ah[t]     + ah[2*F+t] + ah[3*F+t];   // wh1
        g_w[F + t]     = ah[F+t]   + ah[2*F+t] - ah[3*F+t];   // wh2
        g_w[2*F + t]   = al[t];                                // vl1
        g_w[3*F + t]   = al[F+t];                              // vl2
        g_w[4*F + t]   = al[2*F+t] + al[3*F+t];                // vl3
        g_w[5*F + t]   = al[2*F+t] - al[3*F+t];                // vl4
    }
}

// ---------------- K0b: build split/transposed B images ----------------
__global__ void prep_b_kernel(const float* __restrict__ Wh, const float* __restrict__ Wl) {
    int e = blockIdx.x * blockDim.x + threadIdx.x;   // 0..32767
    int n = e >> 8;
    int k = e & 255;
    float v = (n < 64) ? Wh[(size_t)k * F + n] : Wl[(size_t)k * F + (n - 64)];
    __nv_bfloat16 hi, lo;
    split_bf16(v, hi, lo);
    g_Bt_h[e] = hi;
    g_Bt_l[e] = lo;
}

// ---------------- CSR build ----------------
__global__ void zero_deg_kernel(int N) {
    int i = blockIdx.x * blockDim.x + threadIdx.x;
    if (i < N + 4) g_deg[i] = 0;
}

__global__ void count_kernel(const int* __restrict__ src, int E) {
    int i = blockIdx.x * blockDim.x + threadIdx.x;
    int stride = gridDim.x * blockDim.x;
    for (int e = i; e < E; e += stride) atomicAdd(&g_deg[__ldg(src + e)], 1);
}

// 1024 threads, contiguous chunks (multiple of 4), int4-vectorized both phases.
__global__ void scan_kernel(int N) {
    __shared__ int part[1024];
    int t = threadIdx.x;
    int Cc = (((N + 1023) >> 10) + 3) & ~3;
    int base = t * Cc;
    int s = 0;
    for (int i = 0; i < Cc; i += 4) {
        int idx = base + i;
        if (idx < N) {
            int4 v = *(const int4*)&g_deg[idx];   // padded; beyond-N entries are 0
            s += v.x + v.y + v.z + v.w;
        }
    }
    part[t] = s;
    __syncthreads();
    for (int o = 1; o < 1024; o <<= 1) {
        int v = (t >= o) ? part[t - o] : 0;
        __syncthreads();
        part[t] += v;
        __syncthreads();
    }
    int run = part[t] - s;
    for (int i = 0; i < Cc; i += 4) {
        int idx = base + i;
        if (idx < N) {
            int4 v = *(const int4*)&g_deg[idx];
            int4 r;
            r.x = run;
            r.y = r.x + v.x;
            r.z = r.y + v.y;
            r.w = r.z + v.z;
            run = r.w + v.w;
            *(int4*)&g_rs[idx]  = r;
            *(int4*)&g_cur[idx] = r;
        }
    }
}

__global__ void fill_kernel(const int* __restrict__ src, const int* __restrict__ dst, int E) {
    int i = blockIdx.x * blockDim.x + threadIdx.x;
    int stride = gridDim.x * blockDim.x;
    for (int e = i; e < E; e += stride) {
        int s = __ldg(src + e);
        int pos = atomicAdd(&g_cur[s], 1);
        g_csr[pos] = __ldg(dst + e);
    }
}

// ---------------- K1: HMMA split-bf16 GEMM + fused leaky + fused Q scores ----------------
#define ASTRIDE 40   // bf16 elements per smem row (32 + 8 pad)

__global__ void __launch_bounds__(256) gemm_tc_kernel(const float* __restrict__ X, int N) {
    __shared__ __nv_bfloat16 As_h[128 * ASTRIDE];
    __shared__ __nv_bfloat16 As_l[128 * ASTRIDE];
    __shared__ __nv_bfloat16 Bs_h[128 * ASTRIDE];
    __shared__ __nv_bfloat16 Bs_l[128 * ASTRIDE];
    __shared__ float sW[6 * F];        // folded weight vectors
    __shared__ float sQA[128][4];      // high-slab partial dots per row
    __shared__ float sQB[128][2];      // low-slab partial dots per row

    int tid  = threadIdx.x;
    int wid  = tid >> 5;
    int lane = tid & 31;
    int brow = blockIdx.x * 128;
    int warp_m = wid & 3;
    int warp_n = wid >> 2;

    // stage folded weight vectors once
    if (tid < 128) {
        sW[tid]       = g_w[tid];
        sW[tid + 128] = g_w[tid + 128];
        sW[tid + 256] = g_w[tid + 256];
    }

    float acc[2][8][4];
    #pragma unroll
    for (int mi = 0; mi < 2; mi++)
        #pragma unroll
        for (int ni = 0; ni < 8; ni++)
            #pragma unroll
            for (int q = 0; q < 4; q++) acc[mi][ni][q] = 0.f;

    uint32_t sbAH = smem_u32(As_h), sbAL = smem_u32(As_l);
    uint32_t sbBH = smem_u32(Bs_h), sbBL = smem_u32(Bs_l);

    int a_r = lane & 15, a_c = (lane >> 4) << 3;
    int b_r = lane & 7;
    int b_n = ((lane >> 4) & 1) << 3;
    int b_k = ((lane >> 3) & 1) << 3;

    int arow[4], ac4[4];
    #pragma unroll
    for (int i = 0; i < 4; i++) {
        int idx = tid + 256 * i;
        arow[i] = idx >> 3;
        ac4[i]  = (idx & 7) << 2;
    }
    int bn[2], bk[2];
    #pragma unroll
    for (int i = 0; i < 2; i++) {
        int idx = tid + 256 * i;
        bn[i] = idx >> 2;
        bk[i] = (idx & 3) << 3;
    }

    float4 xa[4];
    uint4  pbh[2], pbl[2];

    #pragma unroll
    for (int i = 0; i < 4; i++) {
        int grow = brow + arow[i];
        xa[i] = (grow < N) ? *(const float4*)(X + (size_t)grow * DIN + ac4[i])
                           : make_float4(0.f, 0.f, 0.f, 0.f);
    }
    #pragma unroll
    for (int i = 0; i < 2; i++) {
        pbh[i] = *(const uint4*)(g_Bt_h + (size_t)bn[i] * 256 + bk[i]);
        pbl[i] = *(const uint4*)(g_Bt_l + (size_t)bn[i] * 256 + bk[i]);
    }

    for (int chunk = 0; chunk < 8; chunk++) {
        __syncthreads();
        #pragma unroll
        for (int i = 0; i < 4; i++) {
            float4 v = xa[i];
            __nv_bfloat16 h0, h1, h2, h3, l0, l1, l2, l3;
            split_bf16(v.x, h0, l0); split_bf16(v.y, h1, l1);
            split_bf16(v.z, h2, l2); split_bf16(v.w, h3, l3);
            int o = arow[i] * ASTRIDE + ac4[i];
            __nv_bfloat162 p;
            p.x = h0; p.y = h1; *(__nv_bfloat162*)&As_h[o]     = p;
            p.x = h2; p.y = h3; *(__nv_bfloat162*)&As_h[o + 2] = p;
            p.x = l0; p.y = l1; *(__nv_bfloat162*)&As_l[o]     = p;
            p.x = l2; p.y = l3; *(__nv_bfloat162*)&As_l[o + 2] = p;
        }
        #pragma unroll
        for (int i = 0; i < 2; i++) {
            *(uint4*)&Bs_h[bn[i] * ASTRIDE + bk[i]] = pbh[i];
            *(uint4*)&Bs_l[bn[i] * ASTRIDE + bk[i]] = pbl[i];
        }
        __syncthreads();

        if (chunk < 7) {
            int k0 = (chunk + 1) * 32;
            #pragma unroll
            for (int i = 0; i < 4; i++) {
                int grow = brow + arow[i];
                xa[i] = (grow < N) ? *(const float4*)(X + (size_t)grow * DIN + k0 + ac4[i])
                                   : make_float4(0.f, 0.f, 0.f, 0.f);
            }
            #pragma unroll
            for (int i = 0; i < 2; i++) {
                pbh[i] = *(const uint4*)(g_Bt_h + (size_t)bn[i] * 256 + k0 + bk[i]);
                pbl[i] = *(const uint4*)(g_Bt_l + (size_t)bn[i] * 256 + k0 + bk[i]);
            }
        }

        #pragma unroll
        for (int ks = 0; ks < 2; ks++) {
            int k16 = ks * 16;
            uint32_t ah[2][4], al[2][4];
            #pragma unroll
            for (int mi = 0; mi < 2; mi++) {
                uint32_t aoff = ((warp_m * 32 + mi * 16 + a_r) * ASTRIDE + k16 + a_c) * 2;
                LDMX4(ah[mi][0], ah[mi][1], ah[mi][2], ah[mi][3], sbAH + aoff);
                LDMX4(al[mi][0], al[mi][1], al[mi][2], al[mi][3], sbAL + aoff);
            }
            #pragma unroll
            for (int np = 0; np < 4; np++) {
                uint32_t boff = ((warp_n * 64 + np * 16 + b_n + b_r) * ASTRIDE + k16 + b_k) * 2;
                uint32_t bh[4], bl[4];
                LDMX4(bh[0], bh[1], bh[2], bh[3], sbBH + boff);
                LDMX4(bl[0], bl[1], bl[2], bl[3], sbBL + boff);
                #pragma unroll
                for (int mi = 0; mi < 2; mi++) {
                    #pragma unroll
                    for (int h = 0; h < 2; h++) {
                        float* d = acc[mi][np * 2 + h];
                        MMA16816(d, ah[mi], bh[2 * h], bh[2 * h + 1]);
                        MMA16816(d, ah[mi], bl[2 * h], bl[2 * h + 1]);
                        MMA16816(d, al[mi], bh[2 * h], bh[2 * h + 1]);
                    }
                }
            }
        }
    }

    // --- Epilogue: leaky + store H + fused per-row score dots ---
    __syncthreads();   // all MMAs done before overlay use of smem partial arrays
    int rq   = lane >> 2;            // row-within-16 quad index
    int col0 = warp_n * 64 + ((lane & 3) << 1);
    int cl0  = (lane & 3) << 1;      // local col within the 64-col slab
    float dots[2][2][4];             // [mi][row-half][dot]
    #pragma unroll
    for (int mi = 0; mi < 2; mi++)
        #pragma unroll
        for (int rh = 0; rh < 2; rh++)
            #pragma unroll
            for (int q = 0; q < 4; q++) dots[mi][rh][q] = 0.f;

    #pragma unroll
    for (int mi = 0; mi < 2; mi++) {
        int r0 = brow + warp_m * 32 + mi * 16 + rq;
        #pragma unroll
        for (int ni = 0; ni < 8; ni++) {
            int c  = col0 + ni * 8;
            int lc = cl0 + ni * 8;
            float* d = acc[mi][ni];
            float h0 = leaky(d[0]), h1 = leaky(d[1]);
            float h2 = leaky(d[2]), h3 = leaky(d[3]);
            if (r0 < N)
                *(float2*)&g_ZH[(size_t)r0 * C2 + c] = make_float2(h0, h1);
            if (r0 + 8 < N)
                *(float2*)&g_ZH[(size_t)(r0 + 8) * C2 + c] = make_float2(h2, h3);
            if (warp_n == 0) {
                #pragma unroll
                for (int q = 0; q < 4; q++) {
                    float wa = sW[q * F + lc], wb = sW[q * F + lc + 1];
                    dots[mi][0][q] = fmaf(h0, wa, fmaf(h1, wb, dots[mi][0][q]));
                    dots[mi][1][q] = fmaf(h2, wa, fmaf(h3, wb, dots[mi][1][q]));
                }
            } else {
                #pragma unroll
                for (int q = 0; q < 2; q++) {
                    float wa = sW[(4 + q) * F + lc], wb = sW[(4 + q) * F + lc + 1];
                    dots[mi][0][q] = fmaf(h0, wa, fmaf(h1, wb, dots[mi][0][q]));
                    dots[mi][1][q] = fmaf(h2, wa, fmaf(h3, wb, dots[mi][1][q]));
                }
            }
        }
    }
    // quad-reduce (lanes sharing a row: same lane>>2)
    #pragma unroll
    for (int mi = 0; mi < 2; mi++)
        #pragma unroll
        for (int rh = 0; rh < 2; rh++)
            #pragma unroll
            for (int q = 0; q < 4; q++) {
                float v = dots[mi][rh][q];
                v += __shfl_xor_sync(0xffffffffu, v, 1);
                v += __shfl_xor_sync(0xffffffffu, v, 2);
                dots[mi][rh][q] = v;
            }
    if ((lane & 3) == 0) {
        #pragma unroll
        for (int mi = 0; mi < 2; mi++)
            #pragma unroll
            for (int rh = 0; rh < 2; rh++) {
                int row = warp_m * 32 + mi * 16 + rh * 8 + rq;
                if (warp_n == 0) {
                    sQA[row][0] = dots[mi][rh][0];
                    sQA[row][1] = dots[mi][rh][1];
                    sQA[row][2] = dots[mi][rh][2];
                    sQA[row][3] = dots[mi][rh][3];
                } else {
                    sQB[row][0] = dots[mi][rh][0];
                    sQB[row][1] = dots[mi][rh][1];
                }
            }
    }
    __syncthreads();
    if (tid < 128) {
        int grow = brow + tid;
        if (grow < N) {
            float inh = g_scal[0], inl = g_scal[1];
            g_Q[grow] = make_float4(sQA[tid][0] * inh,
                                    sQA[tid][1] * inh,
                                    (sQA[tid][2] + sQB[tid][0]) * inl,
                                    (sQA[tid][3] + sQB[tid][1]) * inl);
        }
    }
}

// ---------------- K3: CSR aggregation, warp per node, edge-parallel two-phase ----------------
__global__ void __launch_bounds__(256) agg_kernel(float* __restrict__ out, int N) {
    int gw   = (int)(((size_t)blockIdx.x * blockDim.x + threadIdx.x) >> 5);
    int lane = threadIdx.x & 31;
    if (gw >= N) return;
    float4 qs = g_Q[gw];
    int start = g_rs[gw];
    int end   = start + g_deg[gw];
    bool hi = lane < 16;
    float4 acc = make_float4(0.f, 0.f, 0.f, 0.f);
    float rsh = 0.f, rsl = 0.f;
    for (int base = start; base < end; base += 32) {
        int cnt = min(32, end - base);
        // phase 1: one edge per lane — coalesced csr load + parallel Q gather
        int   d_l  = 0;
        float eh_l = 0.f, el_l = 0.f;
        if (lane < cnt) {
            d_l = __ldg(&g_csr[base + lane]);
            float4 qd = __ldg(&g_Q[d_l]);
            float sch = qs.x + qd.y;
            float scl = qs.z + qd.w;
            eh_l = __expf(-fmaxf(sch, 0.2f * sch));
            el_l = __expf(-fmaxf(scl, 0.2f * scl));
        }
        rsh += eh_l;
        rsl += el_l;
        // phase 2: broadcast each edge; H row loads are independent -> high MLP
        for (int j = 0; j < cnt; j++) {
            int   dj  = __shfl_sync(0xffffffffu, d_l, j);
            float ehj = __shfl_sync(0xffffffffu, eh_l, j);
            float elj = __shfl_sync(0xffffffffu, el_l, j);
            float4 hv = __ldg((const float4*)&g_ZH[(size_t)dj * C2 + lane * 4]);
            float ec = hi ? ehj : elj;
            acc.x = fmaf(hv.x, ec, acc.x);
            acc.y = fmaf(hv.y, ec, acc.y);
            acc.z = fmaf(hv.z, ec, acc.z);
            acc.w = fmaf(hv.w, ec, acc.w);
        }
    }
    #pragma unroll
    for (int o = 16; o; o >>= 1) {
        rsh += __shfl_xor_sync(0xffffffffu, rsh, o);
        rsl += __shfl_xor_sync(0xffffffffu, rsl, o);
    }
    float theta = hi ? g_scal[2] : g_scal[3];
    float inv = 1.0f / ((hi ? rsh : rsl) + theta);
    float4 v = make_float4(leaky(acc.x * inv), leaky(acc.y * inv),
                           leaky(acc.z * inv), leaky(acc.w * inv));
    *(float4*)(out + (size_t)gw * C2 + lane * 4) = v;
}

extern "C" void kernel_launch(void* const* d_in, const int* in_sizes, int n_in,
                              void* d_out, int out_size) {
    const float* X    = (const float*)d_in[0];
    const int*   edge = (const int*)d_in[1];
    const float* Wh   = (const float*)d_in[2];
    const float* Wl   = (const float*)d_in[3];
    const float* ah   = (const float*)d_in[4];
    const float* al   = (const float*)d_in[5];
    const float* ch   = (const float*)d_in[6];
    const float* cl   = (const float*)d_in[7];
    float* out = (float*)d_out;

    int N = in_sizes[0] / DIN;
    int E = in_sizes[1] / 2;

    prep_kernel<<<1, 256>>>(ah, al, ch, cl);
    prep_b_kernel<<<128, 256>>>(Wh, Wl);
    zero_deg_kernel<<<(N + 1027) / 1024, 1024>>>(N);
    count_kernel<<<2048, 256>>>(edge, E);
    scan_kernel<<<1, 1024>>>(N);
    fill_kernel<<<2048, 256>>>(edge, edge + E, E);
    gemm_tc_kernel<<<(N + 127) / 128, 256>>>(X, N);
    agg_kernel<<<(N * 32 + 255) / 256, 256>>>(out, N);
}